// round 12
// baseline (speedup 1.0000x reference)
#include <cuda_runtime.h>
#include <math.h>

#define BATCH 32
#define CIN 512
#define HID 64
#define PLANE 4096
#define PLANE4 1024
#define NBASE 8
#define NPLANES (BATCH * CIN)       // 16384
#define NHALF (NPLANES * 2)         // 32768 half-plane tasks
#define HALVES_PER_BATCH (CIN * 2)  // 1024
#define NTASKS (NHALF + NPLANES)    // 49152

#define NTHREADS 256
#define MINBLK 5
#define NBLOCKS (148 * MINBLK)      // 740 (32 KAN + 708 streaming), all resident

// Uniform grid: h = 12/5 = 2.4, t0 = -6 - 3h = -13.2
#define KNOT_T0   (-13.2f)
#define KNOT_INVH (1.0f / 2.4f)

// Scratch (no device allocations allowed)
__device__ float g_part2[NHALF];
__device__ float g_gate[BATCH * CIN];
__device__ unsigned int g_part_done[BATCH];
__device__ volatile unsigned int g_gate_ready[BATCH];
__device__ unsigned int g_ctr = 0;
__device__ unsigned int g_done = 0;

__device__ __forceinline__ float siluf(float v) {
    return v / (1.0f + __expf(-v));
}

// One uniform cubic B-spline basis: q(clamp(u-j,0,4)); exactly matches the
// reference Cox-de Boor recursion on make_grid's uniform knots.
__device__ __forceinline__ float ubasis(float u, float j) {
    float v = fminf(fmaxf(u - j, 0.0f), 4.0f);
    float m1 = fmaxf(v - 1.0f, 0.0f);
    float m2 = fmaxf(v - 2.0f, 0.0f);
    float m3 = fmaxf(v - 3.0f, 0.0f);
    return (v * v * v - 4.0f * m1 * m1 * m1 + 6.0f * m2 * m2 * m2
            - 4.0f * m3 * m3 * m3) * (1.0f / 6.0f);
}

__device__ __forceinline__ float spline_dot8(float x, float4 wa, float4 wb) {
    float u = (x - KNOT_T0) * KNOT_INVH;
    return ubasis(u, 0.0f) * wa.x + ubasis(u, 1.0f) * wa.y
         + ubasis(u, 2.0f) * wa.z + ubasis(u, 3.0f) * wa.w
         + ubasis(u, 4.0f) * wb.x + ubasis(u, 5.0f) * wb.y
         + ubasis(u, 6.0f) * wb.z + ubasis(u, 7.0f) * wb.w;
}

__global__ void __launch_bounds__(NTHREADS, MINBLK) kanse_pipelined(
    const float4* __restrict__ x,
    const float* __restrict__ grid1, const float* __restrict__ bw1,
    const float* __restrict__ sw1,  const float* __restrict__ sc1,
    const float* __restrict__ grid2, const float* __restrict__ bw2,
    const float* __restrict__ sw2,  const float* __restrict__ sc2,
    float4* __restrict__ out) {

    const int lane = threadIdx.x & 31;
    const int wid  = threadIdx.x >> 5;

    __shared__ unsigned int sh_base;
    __shared__ float sh_y1[HID];
    __shared__ float sh_h2[HID];
    __shared__ float4 sh_b2[HID][2];

    // ================= KAN blocks: block b serves batch b ==================
    if (blockIdx.x < BATCH) {
        const int b = blockIdx.x;

        // Wait until all of batch b's half-plane partials are published.
        if (threadIdx.x == 0) {
            while (atomicAdd(&g_part_done[b], 0u) < HALVES_PER_BATCH) {
                __nanosleep(64);
            }
        }
        __syncthreads();
        __threadfence();

        // ---- Layer 1: 8 warps, each handles 8 outputs sequentially ----
        for (int o = wid; o < HID; o += 8) {
            const float4* sw4 = (const float4*)(sw1 + (size_t)o * CIN * NBASE);
            const float*  bwr = bw1 + o * CIN;
            const float*  scr = sc1 + o * CIN;
            float acc = 0.0f;
#pragma unroll 4
            for (int it = 0; it < 16; it++) {
                const int c = lane + 32 * it;
                float2 pr = *(const float2*)(g_part2 + (size_t)(b * CIN + c) * 2);
                float4 wa = sw4[c * 2];
                float4 wb = sw4[c * 2 + 1];
                float bwv = bwr[c];
                float scv = scr[c];
                float m = (pr.x + pr.y) * (1.0f / (float)PLANE);
                if (isnan(m)) m = 0.0f;
                m = fminf(fmaxf(m, -3.402823466e38f), 3.402823466e38f);
                acc += siluf(m) * bwv + spline_dot8(m, wa, wb) * scv;
            }
#pragma unroll
            for (int off = 16; off >= 1; off >>= 1)
                acc += __shfl_xor_sync(0xffffffffu, acc, off);
            if (lane == 0) sh_y1[o] = acc;
        }
        __syncthreads();

        // ---- Inter-layer prep (threads 0..63) ----
        if (threadIdx.x < HID) {
            float h = siluf(sh_y1[threadIdx.x]);
            sh_h2[threadIdx.x] = siluf(h);
            float u = (h - KNOT_T0) * KNOT_INVH;
            float4 ba, bb;
            ba.x = ubasis(u, 0.0f); ba.y = ubasis(u, 1.0f);
            ba.z = ubasis(u, 2.0f); ba.w = ubasis(u, 3.0f);
            bb.x = ubasis(u, 4.0f); bb.y = ubasis(u, 5.0f);
            bb.z = ubasis(u, 6.0f); bb.w = ubasis(u, 7.0f);
            sh_b2[threadIdx.x][0] = ba;
            sh_b2[threadIdx.x][1] = bb;
        }
        __syncthreads();

        // ---- Layer 2 + sigmoid: 8 warps x 64 channels each ----
        for (int c = wid; c < CIN; c += 8) {
            const int j0 = lane * 2;
            const float4* sw4 = (const float4*)(sw2 + (size_t)c * HID * NBASE);
            float4 w0 = sw4[j0 * 2];
            float4 w1 = sw4[j0 * 2 + 1];
            float4 w2 = sw4[j0 * 2 + 2];
            float4 w3 = sw4[j0 * 2 + 3];
            float4 c0 = sh_b2[j0][0];
            float4 c1 = sh_b2[j0][1];
            float4 c2 = sh_b2[j0 + 1][0];
            float4 c3 = sh_b2[j0 + 1][1];
            float sp0 = c0.x * w0.x + c0.y * w0.y + c0.z * w0.z + c0.w * w0.w
                      + c1.x * w1.x + c1.y * w1.y + c1.z * w1.z + c1.w * w1.w;
            float sp1 = c2.x * w2.x + c2.y * w2.y + c2.z * w2.z + c2.w * w2.w
                      + c3.x * w3.x + c3.y * w3.y + c3.z * w3.z + c3.w * w3.w;
            float2 bw = *(const float2*)(bw2 + c * HID + j0);
            float2 sc = *(const float2*)(sc2 + c * HID + j0);
            float acc = sh_h2[j0] * bw.x + sp0 * sc.x
                      + sh_h2[j0 + 1] * bw.y + sp1 * sc.y;
#pragma unroll
            for (int off = 16; off >= 1; off >>= 1)
                acc += __shfl_xor_sync(0xffffffffu, acc, off);
            if (lane == 0) g_gate[b * CIN + c] = 1.0f / (1.0f + __expf(-acc));
        }

        // Publish
        __threadfence();
        __syncthreads();
        if (threadIdx.x == 0) g_gate_ready[b] = 1u;
        // fall through to streaming
    }

    // ================= Streaming: single ordered work queue =================
    for (;;) {
        __syncthreads();
        if (threadIdx.x == 0) sh_base = atomicAdd(&g_ctr, 8u);
        __syncthreads();
        const unsigned task = sh_base + wid;
        if (sh_base >= (unsigned)NTASKS) break;
        if (task >= (unsigned)NTASKS) continue;

        if (task < (unsigned)NHALF) {
            // ---- Phase 1: half-plane partial sum ----
            const int e = task;
            const float4* p = x + (size_t)e * 512;
            float sum = 0.0f;
#pragma unroll
            for (int half = 0; half < 2; half++) {
                float4 r[8];
#pragma unroll
                for (int u = 0; u < 8; u++)
                    r[u] = p[half * 256 + u * 32 + lane];
#pragma unroll
                for (int u = 0; u < 8; u++)
                    sum += (r[u].x + r[u].y) + (r[u].z + r[u].w);
            }
#pragma unroll
            for (int off = 16; off >= 1; off >>= 1)
                sum += __shfl_xor_sync(0xffffffffu, sum, off);
            if (lane == 0) {
                g_part2[e] = sum;
                __threadfence();
                atomicAdd(&g_part_done[e / HALVES_PER_BATCH], 1u);
            }
        } else {
            // ---- Phase 3: apply gate to one plane ----
            const int plane = task - NHALF;
            const int b = plane >> 9;
            if (lane == 0) {
                while (g_gate_ready[b] == 0u) { __nanosleep(64); }
            }
            __syncwarp();
            __threadfence();
            const float g = g_gate[plane];
            const float4* p = x + (size_t)plane * PLANE4;
            float4* q = out + (size_t)plane * PLANE4;
#pragma unroll
            for (int it = 0; it < 4; it++) {
                const int o0 = it * 256 + lane;
                float4 r[8];
#pragma unroll
                for (int u = 0; u < 8; u++)
                    r[u] = p[o0 + u * 32];
#pragma unroll
                for (int u = 0; u < 8; u++) {
                    r[u].x *= g; r[u].y *= g; r[u].z *= g; r[u].w *= g;
                    __stcs(&q[o0 + u * 32], r[u]);
                }
            }
        }
    }

    // ================= Reset state for next graph replay =====================
    __syncthreads();
    if (threadIdx.x == 0) {
        __threadfence();
        unsigned int old = atomicAdd(&g_done, 1u);
        if (old == NBLOCKS - 1) {
            g_ctr = 0;
            for (int b = 0; b < BATCH; b++) {
                g_part_done[b] = 0;
                g_gate_ready[b] = 0;
            }
            g_done = 0;
            __threadfence();
        }
    }
}

extern "C" void kernel_launch(void* const* d_in, const int* in_sizes, int n_in,
                              void* d_out, int out_size) {
    const float* x     = (const float*)d_in[0];
    const float* grid1 = (const float*)d_in[1];
    const float* bw1   = (const float*)d_in[2];
    const float* sw1   = (const float*)d_in[3];
    const float* sc1   = (const float*)d_in[4];
    const float* grid2 = (const float*)d_in[5];
    const float* bw2   = (const float*)d_in[6];
    const float* sw2   = (const float*)d_in[7];
    const float* sc2   = (const float*)d_in[8];
    float* out = (float*)d_out;

    kanse_pipelined<<<NBLOCKS, NTHREADS>>>(
        (const float4*)x, grid1, bw1, sw1, sc1,
        grid2, bw2, sw2, sc2, (float4*)out);
}

// round 13
// speedup vs baseline: 1.0116x; 1.0116x over previous
#include <cuda_runtime.h>
#include <math.h>

#define BATCH 32
#define CIN 512
#define HID 64
#define PLANE 4096
#define PLANE4 1024
#define NBASE 8
#define NPLANES (BATCH * CIN)       // 16384
#define NHALF (NPLANES * 2)         // 32768 half-plane tasks
#define HALVES_PER_BATCH (CIN * 2)  // 1024
#define NTASKS (NHALF + NPLANES)    // 49152

#define NTHREADS 256
#define MINBLK 5
#define NBLOCKS (148 * MINBLK)      // 740 (32 KAN + 708 streaming), all resident

// Uniform grid: h = 12/5 = 2.4, t0 = -6 - 3h = -13.2
#define KNOT_T0   (-13.2f)
#define KNOT_INVH (1.0f / 2.4f)

// Scratch (no device allocations allowed)
__device__ float g_part2[NHALF];
__device__ float g_gate[BATCH * CIN];
__device__ unsigned int g_part_done[BATCH];
__device__ unsigned int g_gate_ready[BATCH];
__device__ unsigned int g_ctr = 0;
__device__ unsigned int g_done = 0;

__device__ __forceinline__ unsigned ld_acquire(const unsigned* p) {
    unsigned v;
    asm volatile("ld.acquire.gpu.u32 %0, [%1];" : "=r"(v) : "l"(p) : "memory");
    return v;
}

__device__ __forceinline__ void st_release(unsigned* p, unsigned v) {
    asm volatile("st.release.gpu.u32 [%0], %1;" :: "l"(p), "r"(v) : "memory");
}

__device__ __forceinline__ float siluf(float v) {
    return v / (1.0f + __expf(-v));
}

// One uniform cubic B-spline basis: q(clamp(u-j,0,4)); exactly matches the
// reference Cox-de Boor recursion on make_grid's uniform knots.
__device__ __forceinline__ float ubasis(float u, float j) {
    float v = fminf(fmaxf(u - j, 0.0f), 4.0f);
    float m1 = fmaxf(v - 1.0f, 0.0f);
    float m2 = fmaxf(v - 2.0f, 0.0f);
    float m3 = fmaxf(v - 3.0f, 0.0f);
    return (v * v * v - 4.0f * m1 * m1 * m1 + 6.0f * m2 * m2 * m2
            - 4.0f * m3 * m3 * m3) * (1.0f / 6.0f);
}

__device__ __forceinline__ float spline_dot8(float x, float4 wa, float4 wb) {
    float u = (x - KNOT_T0) * KNOT_INVH;
    return ubasis(u, 0.0f) * wa.x + ubasis(u, 1.0f) * wa.y
         + ubasis(u, 2.0f) * wa.z + ubasis(u, 3.0f) * wa.w
         + ubasis(u, 4.0f) * wb.x + ubasis(u, 5.0f) * wb.y
         + ubasis(u, 6.0f) * wb.z + ubasis(u, 7.0f) * wb.w;
}

__global__ void __launch_bounds__(NTHREADS, MINBLK) kanse_pipelined(
    const float4* __restrict__ x,
    const float* __restrict__ grid1, const float* __restrict__ bw1,
    const float* __restrict__ sw1,  const float* __restrict__ sc1,
    const float* __restrict__ grid2, const float* __restrict__ bw2,
    const float* __restrict__ sw2,  const float* __restrict__ sc2,
    float4* __restrict__ out) {

    const int lane = threadIdx.x & 31;
    const int wid  = threadIdx.x >> 5;

    __shared__ unsigned int sh_base;
    __shared__ float sh_y1[HID];
    __shared__ float sh_h2[HID];
    __shared__ float4 sh_b2[HID][2];

    // ================= KAN blocks: block b serves batch b ==================
    if (blockIdx.x < BATCH) {
        const int b = blockIdx.x;

        // Wait until all of batch b's half-plane partials are published.
        if (threadIdx.x == 0) {
            while (ld_acquire(&g_part_done[b]) < HALVES_PER_BATCH) {
                __nanosleep(64);
            }
        }
        __syncthreads();

        // ---- Layer 1: 8 warps, each handles 8 outputs sequentially ----
        for (int o = wid; o < HID; o += 8) {
            const float4* sw4 = (const float4*)(sw1 + (size_t)o * CIN * NBASE);
            const float*  bwr = bw1 + o * CIN;
            const float*  scr = sc1 + o * CIN;
            float acc = 0.0f;
#pragma unroll 4
            for (int it = 0; it < 16; it++) {
                const int c = lane + 32 * it;
                float2 pr = *(const float2*)(g_part2 + (size_t)(b * CIN + c) * 2);
                float4 wa = sw4[c * 2];
                float4 wb = sw4[c * 2 + 1];
                float bwv = bwr[c];
                float scv = scr[c];
                float m = (pr.x + pr.y) * (1.0f / (float)PLANE);
                if (isnan(m)) m = 0.0f;
                m = fminf(fmaxf(m, -3.402823466e38f), 3.402823466e38f);
                acc += siluf(m) * bwv + spline_dot8(m, wa, wb) * scv;
            }
#pragma unroll
            for (int off = 16; off >= 1; off >>= 1)
                acc += __shfl_xor_sync(0xffffffffu, acc, off);
            if (lane == 0) sh_y1[o] = acc;
        }
        __syncthreads();

        // ---- Inter-layer prep (threads 0..63) ----
        if (threadIdx.x < HID) {
            float h = siluf(sh_y1[threadIdx.x]);
            sh_h2[threadIdx.x] = siluf(h);
            float u = (h - KNOT_T0) * KNOT_INVH;
            float4 ba, bb;
            ba.x = ubasis(u, 0.0f); ba.y = ubasis(u, 1.0f);
            ba.z = ubasis(u, 2.0f); ba.w = ubasis(u, 3.0f);
            bb.x = ubasis(u, 4.0f); bb.y = ubasis(u, 5.0f);
            bb.z = ubasis(u, 6.0f); bb.w = ubasis(u, 7.0f);
            sh_b2[threadIdx.x][0] = ba;
            sh_b2[threadIdx.x][1] = bb;
        }
        __syncthreads();

        // ---- Layer 2 + sigmoid: 8 warps x 64 channels each ----
        for (int c = wid; c < CIN; c += 8) {
            const int j0 = lane * 2;
            const float4* sw4 = (const float4*)(sw2 + (size_t)c * HID * NBASE);
            float4 w0 = sw4[j0 * 2];
            float4 w1 = sw4[j0 * 2 + 1];
            float4 w2 = sw4[j0 * 2 + 2];
            float4 w3 = sw4[j0 * 2 + 3];
            float4 c0 = sh_b2[j0][0];
            float4 c1 = sh_b2[j0][1];
            float4 c2 = sh_b2[j0 + 1][0];
            float4 c3 = sh_b2[j0 + 1][1];
            float sp0 = c0.x * w0.x + c0.y * w0.y + c0.z * w0.z + c0.w * w0.w
                      + c1.x * w1.x + c1.y * w1.y + c1.z * w1.z + c1.w * w1.w;
            float sp1 = c2.x * w2.x + c2.y * w2.y + c2.z * w2.z + c2.w * w2.w
                      + c3.x * w3.x + c3.y * w3.y + c3.z * w3.z + c3.w * w3.w;
            float2 bw = *(const float2*)(bw2 + c * HID + j0);
            float2 sc = *(const float2*)(sc2 + c * HID + j0);
            float acc = sh_h2[j0] * bw.x + sp0 * sc.x
                      + sh_h2[j0 + 1] * bw.y + sp1 * sc.y;
#pragma unroll
            for (int off = 16; off >= 1; off >>= 1)
                acc += __shfl_xor_sync(0xffffffffu, acc, off);
            if (lane == 0) g_gate[b * CIN + c] = 1.0f / (1.0f + __expf(-acc));
        }

        // Publish: per-thread fence (one-time), then release-store the flag.
        __threadfence();
        __syncthreads();
        if (threadIdx.x == 0) st_release(&g_gate_ready[b], 1u);
        // fall through to streaming
    }

    // ================= Streaming: single ordered work queue =================
    for (;;) {
        __syncthreads();
        if (threadIdx.x == 0) sh_base = atomicAdd(&g_ctr, 8u);
        __syncthreads();
        const unsigned task = sh_base + wid;
        if (sh_base >= (unsigned)NTASKS) break;
        if (task >= (unsigned)NTASKS) continue;

        if (task < (unsigned)NHALF) {
            // ---- Phase 1: half-plane partial sum ----
            const int e = task;
            const float4* p = x + (size_t)e * 512;
            float sum = 0.0f;
#pragma unroll
            for (int half = 0; half < 2; half++) {
                float4 r[8];
#pragma unroll
                for (int u = 0; u < 8; u++)
                    r[u] = p[half * 256 + u * 32 + lane];
#pragma unroll
                for (int u = 0; u < 8; u++)
                    sum += (r[u].x + r[u].y) + (r[u].z + r[u].w);
            }
#pragma unroll
            for (int off = 16; off >= 1; off >>= 1)
                sum += __shfl_xor_sync(0xffffffffu, sum, off);
            if (lane == 0) {
                g_part2[e] = sum;
                __threadfence();   // covers only lane0's tiny stores
                atomicAdd(&g_part_done[e / HALVES_PER_BATCH], 1u);
            }
        } else {
            // ---- Phase 3: apply gate to one plane (no fences in hot path) --
            const int plane = task - NHALF;
            const int b = plane >> 9;
            float g;
            if (lane == 0) {
                // acquire-spin (normally already set: single acquire load)
                while (ld_acquire(&g_gate_ready[b]) == 0u) { __nanosleep(64); }
                g = g_gate[plane];   // same-thread load, ordered after acquire
            }
            g = __shfl_sync(0xffffffffu, g, 0);

            const float4* p = x + (size_t)plane * PLANE4;
            float4* q = out + (size_t)plane * PLANE4;
#pragma unroll
            for (int it = 0; it < 4; it++) {
                const int o0 = it * 256 + lane;
                float4 r[8];
#pragma unroll
                for (int u = 0; u < 8; u++)
                    r[u] = p[o0 + u * 32];
#pragma unroll
                for (int u = 0; u < 8; u++) {
                    r[u].x *= g; r[u].y *= g; r[u].z *= g; r[u].w *= g;
                    __stcs(&q[o0 + u * 32], r[u]);
                }
            }
        }
    }

    // ================= Reset state for next graph replay =====================
    __syncthreads();
    if (threadIdx.x == 0) {
        __threadfence();
        unsigned int old = atomicAdd(&g_done, 1u);
        if (old == NBLOCKS - 1) {
            g_ctr = 0;
            for (int b = 0; b < BATCH; b++) {
                g_part_done[b] = 0;
                g_gate_ready[b] = 0;
            }
            g_done = 0;
            __threadfence();
        }
    }
}

extern "C" void kernel_launch(void* const* d_in, const int* in_sizes, int n_in,
                              void* d_out, int out_size) {
    const float* x     = (const float*)d_in[0];
    const float* grid1 = (const float*)d_in[1];
    const float* bw1   = (const float*)d_in[2];
    const float* sw1   = (const float*)d_in[3];
    const float* sc1   = (const float*)d_in[4];
    const float* grid2 = (const float*)d_in[5];
    const float* bw2   = (const float*)d_in[6];
    const float* sw2   = (const float*)d_in[7];
    const float* sc2   = (const float*)d_in[8];
    float* out = (float*)d_out;

    kanse_pipelined<<<NBLOCKS, NTHREADS>>>(
        (const float4*)x, grid1, bw1, sw1, sc1,
        grid2, bw2, sw2, sc2, (float4*)out);
}

// round 14
// speedup vs baseline: 1.8241x; 1.8032x over previous
#include <cuda_runtime.h>
#include <math.h>

#define BATCH 32
#define CIN 512
#define HID 64
#define PLANE 4096
#define PLANE4 1024
#define NBASE 8
#define NPLANES (BATCH * CIN)     // 16384
#define NHALF (NPLANES * 2)       // 32768 half-plane tasks

#define NTHREADS 256
#define MINBLK 5
#define NBLOCKS (148 * MINBLK)               // 740, all resident
#define NWARPS (NBLOCKS * (NTHREADS / 32))   // 5920

#define WCH1 4     // half-plane tasks per WARP grab in phase 1
#define WCH3 2     // planes per WARP grab in phase 3

// Uniform grid: h = 12/5 = 2.4, t0 = -6 - 3h = -13.2
#define KNOT_T0   (-13.2f)
#define KNOT_INVH (1.0f / 2.4f)

// Scratch (no device allocations allowed)
__device__ float  g_part2[NHALF];
__device__ float  g_h2silu[BATCH * HID];
__device__ float4 g_b2[BATCH * HID * 2];

__device__ unsigned int g_ctr1 = 0;
__device__ unsigned int g_ctr3 = 0;
__device__ unsigned int g_done = 0;
__device__ unsigned int g_bar_count = 0;
__device__ volatile unsigned int g_bar_gen = 0;

__device__ __forceinline__ void grid_barrier() {
    __threadfence();
    __syncthreads();
    if (threadIdx.x == 0) {
        unsigned int gen = g_bar_gen;
        unsigned int old = atomicAdd(&g_bar_count, 1u);
        if (old == NBLOCKS - 1) {
            g_bar_count = 0;
            __threadfence();
            g_bar_gen = gen + 1;
        } else {
            while (g_bar_gen == gen) { __nanosleep(32); }
        }
        __threadfence();
    }
    __syncthreads();
}

__device__ __forceinline__ float siluf(float v) {
    return v / (1.0f + __expf(-v));
}

// One uniform cubic B-spline basis: q(clamp(u-j,0,4)); exactly matches the
// reference Cox-de Boor recursion on make_grid's uniform knots.
__device__ __forceinline__ float ubasis(float u, float j) {
    float v = fminf(fmaxf(u - j, 0.0f), 4.0f);
    float m1 = fmaxf(v - 1.0f, 0.0f);
    float m2 = fmaxf(v - 2.0f, 0.0f);
    float m3 = fmaxf(v - 3.0f, 0.0f);
    return (v * v * v - 4.0f * m1 * m1 * m1 + 6.0f * m2 * m2 * m2
            - 4.0f * m3 * m3 * m3) * (1.0f / 6.0f);
}

__device__ __forceinline__ float spline_dot8(float x, float4 wa, float4 wb) {
    float u = (x - KNOT_T0) * KNOT_INVH;
    return ubasis(u, 0.0f) * wa.x + ubasis(u, 1.0f) * wa.y
         + ubasis(u, 2.0f) * wa.z + ubasis(u, 3.0f) * wa.w
         + ubasis(u, 4.0f) * wb.x + ubasis(u, 5.0f) * wb.y
         + ubasis(u, 6.0f) * wb.z + ubasis(u, 7.0f) * wb.w;
}

__global__ void __launch_bounds__(NTHREADS, MINBLK) kanse_persistent(
    const float4* __restrict__ x,
    const float* __restrict__ grid1, const float* __restrict__ bw1,
    const float* __restrict__ sw1,  const float* __restrict__ sc1,
    const float* __restrict__ grid2, const float* __restrict__ bw2,
    const float* __restrict__ sw2,  const float* __restrict__ sc2,
    float4* __restrict__ out) {

    const int lane = threadIdx.x & 31;
    const int wid  = threadIdx.x >> 5;
    const int w = blockIdx.x * (NTHREADS / 32) + wid;

    // ===== Phase 1: half-plane sums, per-WARP stealing, REVERSE order ======
    for (;;) {
        unsigned base;
        if (lane == 0) base = atomicAdd(&g_ctr1, (unsigned)WCH1);
        base = __shfl_sync(0xffffffffu, base, 0);
        if (base >= NHALF) break;
        unsigned rbase = NHALF - WCH1 - base;   // reverse mapping (L2 tail reuse)
#pragma unroll
        for (int k = 0; k < WCH1; k++) {
            const int e = rbase + k;
            const float4* p = x + (size_t)e * 512;
            float sum = 0.0f;
#pragma unroll
            for (int half = 0; half < 2; half++) {
                float4 r[8];
#pragma unroll
                for (int u = 0; u < 8; u++)
                    r[u] = p[half * 256 + u * 32 + lane];
#pragma unroll
                for (int u = 0; u < 8; u++)
                    sum += (r[u].x + r[u].y) + (r[u].z + r[u].w);
            }
#pragma unroll
            for (int off = 16; off >= 1; off >>= 1)
                sum += __shfl_xor_sync(0xffffffffu, sum, off);
            if (lane == 0) g_part2[e] = sum;
        }
    }

    grid_barrier();

    // ===== Phase 2a: layer 1 (warp per (b,o)); mean-combine + prep inline ===
    if (w < BATCH * HID) {
        const int b = w >> 6;
        const int o = w & (HID - 1);
        const float4* sw4 = (const float4*)(sw1 + (size_t)o * CIN * NBASE);
        const float*  bwr = bw1 + o * CIN;
        const float*  scr = sc1 + o * CIN;

        float acc = 0.0f;
#pragma unroll 4
        for (int it = 0; it < 16; it++) {
            const int c = lane + 32 * it;
            float2 pr = *(const float2*)(g_part2 + (size_t)(b * CIN + c) * 2);
            float4 wa = sw4[c * 2];
            float4 wb = sw4[c * 2 + 1];
            float bwv = bwr[c];
            float scv = scr[c];

            float m = (pr.x + pr.y) * (1.0f / (float)PLANE);
            if (isnan(m)) m = 0.0f;

            acc += siluf(m) * bwv + spline_dot8(m, wa, wb) * scv;
        }
#pragma unroll
        for (int off = 16; off >= 1; off >>= 1)
            acc += __shfl_xor_sync(0xffffffffu, acc, off);

        if (lane == 0) {
            float h = siluf(acc);
            g_h2silu[b * HID + o] = siluf(h);
            float u = (h - KNOT_T0) * KNOT_INVH;
            float4 ba, bb;
            ba.x = ubasis(u, 0.0f); ba.y = ubasis(u, 1.0f);
            ba.z = ubasis(u, 2.0f); ba.w = ubasis(u, 3.0f);
            bb.x = ubasis(u, 4.0f); bb.y = ubasis(u, 5.0f);
            bb.z = ubasis(u, 6.0f); bb.w = ubasis(u, 7.0f);
            g_b2[(b * HID + o) * 2]     = ba;
            g_b2[(b * HID + o) * 2 + 1] = bb;
        }
    }

    grid_barrier();

    // ===== Phase 3: inline gate + apply, per-WARP stealing ==================
    for (;;) {
        unsigned base;
        if (lane == 0) base = atomicAdd(&g_ctr3, (unsigned)WCH3);
        base = __shfl_sync(0xffffffffu, base, 0);
        if (base >= (unsigned)NPLANES) break;
#pragma unroll
        for (int k = 0; k < WCH3; k++) {
            const int plane = base + k;
            const int b = plane >> 9;
            const int c = plane & (CIN - 1);

            // ---- gate(b,c): 64-dot with spline path (lane covers j0,j0+1) --
            const int j0 = lane * 2;
            const float4* sw4 = (const float4*)(sw2 + (size_t)c * HID * NBASE);
            float4 w0 = sw4[j0 * 2];
            float4 w1 = sw4[j0 * 2 + 1];
            float4 w2 = sw4[j0 * 2 + 2];
            float4 w3 = sw4[j0 * 2 + 3];
            float4 c0 = g_b2[(b * HID + j0) * 2];
            float4 c1 = g_b2[(b * HID + j0) * 2 + 1];
            float4 c2 = g_b2[(b * HID + j0 + 1) * 2];
            float4 c3 = g_b2[(b * HID + j0 + 1) * 2 + 1];
            float sp0 = c0.x * w0.x + c0.y * w0.y + c0.z * w0.z + c0.w * w0.w
                      + c1.x * w1.x + c1.y * w1.y + c1.z * w1.z + c1.w * w1.w;
            float sp1 = c2.x * w2.x + c2.y * w2.y + c2.z * w2.z + c2.w * w2.w
                      + c3.x * w3.x + c3.y * w3.y + c3.z * w3.z + c3.w * w3.w;
            float2 bw = *(const float2*)(bw2 + c * HID + j0);
            float2 sc = *(const float2*)(sc2 + c * HID + j0);
            float2 h2 = *(const float2*)(g_h2silu + b * HID + j0);
            float acc = h2.x * bw.x + sp0 * sc.x + h2.y * bw.y + sp1 * sc.y;
#pragma unroll
            for (int off = 16; off >= 1; off >>= 1)
                acc += __shfl_xor_sync(0xffffffffu, acc, off);
            const float g = 1.0f / (1.0f + __expf(-acc));

            // ---- stream the plane: 4 iterations of 8 front-batched float4 --
            const float4* p = x + (size_t)plane * PLANE4;
            float4* q = out + (size_t)plane * PLANE4;
#pragma unroll
            for (int it = 0; it < 4; it++) {
                const int o0 = it * 256 + lane;
                float4 r[8];
#pragma unroll
                for (int u = 0; u < 8; u++)
                    r[u] = p[o0 + u * 32];
#pragma unroll
                for (int u = 0; u < 8; u++) {
                    r[u].x *= g; r[u].y *= g; r[u].z *= g; r[u].w *= g;
                    __stcs(&q[o0 + u * 32], r[u]);
                }
            }
        }
    }

    // ===== Reset counters for next graph replay (last block) ================
    __syncthreads();
    if (threadIdx.x == 0) {
        __threadfence();
        unsigned int old = atomicAdd(&g_done, 1u);
        if (old == NBLOCKS - 1) {
            g_ctr1 = 0;
            g_ctr3 = 0;
            g_done = 0;
            __threadfence();
        }
    }
}

extern "C" void kernel_launch(void* const* d_in, const int* in_sizes, int n_in,
                              void* d_out, int out_size) {
    const float* x     = (const float*)d_in[0];
    const float* grid1 = (const float*)d_in[1];
    const float* bw1   = (const float*)d_in[2];
    const float* sw1   = (const float*)d_in[3];
    const float* sc1   = (const float*)d_in[4];
    const float* grid2 = (const float*)d_in[5];
    const float* bw2   = (const float*)d_in[6];
    const float* sw2   = (const float*)d_in[7];
    const float* sc2   = (const float*)d_in[8];
    float* out = (float*)d_out;

    kanse_persistent<<<NBLOCKS, NTHREADS>>>(
        (const float4*)x, grid1, bw1, sw1, sc1,
        grid2, bw2, sw2, sc2, (float4*)out);
}

// round 15
// speedup vs baseline: 1.8768x; 1.0289x over previous
#include <cuda_runtime.h>
#include <math.h>

#define BATCH 32
#define CIN 512
#define HID 64
#define PLANE 4096
#define PLANE4 1024
#define NBASE 8
#define NPLANES (BATCH * CIN)     // 16384

#define NTHREADS 256
#define MINBLK 6
#define NBLOCKS (148 * MINBLK)               // 888, all resident
#define NWARPS (NBLOCKS * (NTHREADS / 32))   // 7104

// Uniform grid: h = 12/5 = 2.4, t0 = -6 - 3h = -13.2
#define KNOT_T0   (-13.2f)
#define KNOT_INVH (1.0f / 2.4f)

// Scratch (no device allocations allowed) — all written every replay
__device__ float  g_mean[NPLANES];
__device__ float  g_h2silu[BATCH * HID];
__device__ float4 g_b2[BATCH * HID * 2];
__device__ float  g_gate[NPLANES];

__device__ unsigned int g_bar_count = 0;
__device__ volatile unsigned int g_bar_gen = 0;

__device__ __forceinline__ void grid_barrier() {
    __threadfence();
    __syncthreads();
    if (threadIdx.x == 0) {
        unsigned int gen = g_bar_gen;
        unsigned int old = atomicAdd(&g_bar_count, 1u);
        if (old == NBLOCKS - 1) {
            g_bar_count = 0;
            __threadfence();
            g_bar_gen = gen + 1;
        } else {
            while (g_bar_gen == gen) { __nanosleep(32); }
        }
        __threadfence();
    }
    __syncthreads();
}

__device__ __forceinline__ float siluf(float v) {
    return v / (1.0f + __expf(-v));
}

// One uniform cubic B-spline basis: q(clamp(u-j,0,4)); exactly matches the
// reference Cox-de Boor recursion on make_grid's uniform knots.
__device__ __forceinline__ float ubasis(float u, float j) {
    float v = fminf(fmaxf(u - j, 0.0f), 4.0f);
    float m1 = fmaxf(v - 1.0f, 0.0f);
    float m2 = fmaxf(v - 2.0f, 0.0f);
    float m3 = fmaxf(v - 3.0f, 0.0f);
    return (v * v * v - 4.0f * m1 * m1 * m1 + 6.0f * m2 * m2 * m2
            - 4.0f * m3 * m3 * m3) * (1.0f / 6.0f);
}

__device__ __forceinline__ float spline_dot8(float x, float4 wa, float4 wb) {
    float u = (x - KNOT_T0) * KNOT_INVH;
    return ubasis(u, 0.0f) * wa.x + ubasis(u, 1.0f) * wa.y
         + ubasis(u, 2.0f) * wa.z + ubasis(u, 3.0f) * wa.w
         + ubasis(u, 4.0f) * wb.x + ubasis(u, 5.0f) * wb.y
         + ubasis(u, 6.0f) * wb.z + ubasis(u, 7.0f) * wb.w;
}

__global__ void __launch_bounds__(NTHREADS, MINBLK) kanse_persistent(
    const float4* __restrict__ x,
    const float* __restrict__ grid1, const float* __restrict__ bw1,
    const float* __restrict__ sw1,  const float* __restrict__ sc1,
    const float* __restrict__ grid2, const float* __restrict__ bw2,
    const float* __restrict__ sw2,  const float* __restrict__ sc2,
    float4* __restrict__ out) {

    const int lane = threadIdx.x & 31;
    const int wid  = threadIdx.x >> 5;
    const int w = blockIdx.x * (NTHREADS / 32) + wid;

    __shared__ float ws[8];

    // ===== Phase 1: plane mean — block-cooperative, standalone-clone ========
    // Reverse plane order so the last-read planes (head of x) stay in L2 for
    // phase 3's forward start.
    for (int iv = blockIdx.x; iv < NPLANES; iv += NBLOCKS) {
        const int plane = NPLANES - 1 - iv;
        const float4* p = x + (size_t)plane * PLANE4;
        float4 v0 = p[threadIdx.x];
        float4 v1 = p[256 + threadIdx.x];
        float4 v2 = p[512 + threadIdx.x];
        float4 v3 = p[768 + threadIdx.x];
        float sum = ((v0.x + v0.y) + (v0.z + v0.w)) + ((v1.x + v1.y) + (v1.z + v1.w))
                  + ((v2.x + v2.y) + (v2.z + v2.w)) + ((v3.x + v3.y) + (v3.z + v3.w));
#pragma unroll
        for (int off = 16; off >= 1; off >>= 1)
            sum += __shfl_xor_sync(0xffffffffu, sum, off);
        if (lane == 0) ws[wid] = sum;
        __syncthreads();
        if (threadIdx.x == 0) {
            float tot = ((ws[0] + ws[1]) + (ws[2] + ws[3]))
                      + ((ws[4] + ws[5]) + (ws[6] + ws[7]));
            float m = tot * (1.0f / (float)PLANE);
            if (isnan(m)) m = 0.0f;
            m = fminf(fmaxf(m, -3.402823466e38f), 3.402823466e38f);
            g_mean[plane] = m;
        }
        __syncthreads();   // protect ws before next iteration
    }

    grid_barrier();

    // ===== Phase 2a: layer 1 (warp per (b,o)) ==============================
    if (w < BATCH * HID) {
        const int b = w >> 6;
        const int o = w & (HID - 1);
        const float4* sw4 = (const float4*)(sw1 + (size_t)o * CIN * NBASE);
        const float*  bwr = bw1 + o * CIN;
        const float*  scr = sc1 + o * CIN;

        float acc = 0.0f;
#pragma unroll 4
        for (int it = 0; it < 16; it++) {
            const int c = lane + 32 * it;
            float m   = g_mean[b * CIN + c];
            float4 wa = sw4[c * 2];
            float4 wb = sw4[c * 2 + 1];
            float bwv = bwr[c];
            float scv = scr[c];
            acc += siluf(m) * bwv + spline_dot8(m, wa, wb) * scv;
        }
#pragma unroll
        for (int off = 16; off >= 1; off >>= 1)
            acc += __shfl_xor_sync(0xffffffffu, acc, off);

        if (lane == 0) {
            float h = siluf(acc);
            g_h2silu[b * HID + o] = siluf(h);
            float u = (h - KNOT_T0) * KNOT_INVH;
            float4 ba, bb;
            ba.x = ubasis(u, 0.0f); ba.y = ubasis(u, 1.0f);
            ba.z = ubasis(u, 2.0f); ba.w = ubasis(u, 3.0f);
            bb.x = ubasis(u, 4.0f); bb.y = ubasis(u, 5.0f);
            bb.z = ubasis(u, 6.0f); bb.w = ubasis(u, 7.0f);
            g_b2[(b * HID + o) * 2]     = ba;
            g_b2[(b * HID + o) * 2 + 1] = bb;
        }
    }

    grid_barrier();

    // ===== Phase 2b: layer 2 + sigmoid (warp per (b,c), static) ============
    for (int t = w; t < NPLANES; t += NWARPS) {
        const int b = t >> 9;
        const int c = t & (CIN - 1);
        const int j0 = lane * 2;
        const float4* sw4 = (const float4*)(sw2 + (size_t)c * HID * NBASE);

        float4 w0 = sw4[j0 * 2];
        float4 w1 = sw4[j0 * 2 + 1];
        float4 w2 = sw4[j0 * 2 + 2];
        float4 w3 = sw4[j0 * 2 + 3];
        float4 c0 = g_b2[(b * HID + j0) * 2];
        float4 c1 = g_b2[(b * HID + j0) * 2 + 1];
        float4 c2 = g_b2[(b * HID + j0 + 1) * 2];
        float4 c3 = g_b2[(b * HID + j0 + 1) * 2 + 1];
        float sp0 = c0.x * w0.x + c0.y * w0.y + c0.z * w0.z + c0.w * w0.w
                  + c1.x * w1.x + c1.y * w1.y + c1.z * w1.z + c1.w * w1.w;
        float sp1 = c2.x * w2.x + c2.y * w2.y + c2.z * w2.z + c2.w * w2.w
                  + c3.x * w3.x + c3.y * w3.y + c3.z * w3.z + c3.w * w3.w;
        float2 bw = *(const float2*)(bw2 + c * HID + j0);
        float2 sc = *(const float2*)(sc2 + c * HID + j0);
        float2 h2 = *(const float2*)(g_h2silu + b * HID + j0);
        float acc = h2.x * bw.x + sp0 * sc.x + h2.y * bw.y + sp1 * sc.y;
#pragma unroll
        for (int off = 16; off >= 1; off >>= 1)
            acc += __shfl_xor_sync(0xffffffffu, acc, off);
        if (lane == 0)
            g_gate[t] = 1.0f / (1.0f + __expf(-acc));
    }

    grid_barrier();

    // ===== Phase 3: apply — block-cooperative, standalone-clone, forward ===
    for (int plane = blockIdx.x; plane < NPLANES; plane += NBLOCKS) {
        const float g = g_gate[plane];
        const float4* p = x + (size_t)plane * PLANE4;
        float4* q = out + (size_t)plane * PLANE4;
        float4 v0 = p[threadIdx.x];
        float4 v1 = p[256 + threadIdx.x];
        float4 v2 = p[512 + threadIdx.x];
        float4 v3 = p[768 + threadIdx.x];
        v0.x *= g; v0.y *= g; v0.z *= g; v0.w *= g;
        v1.x *= g; v1.y *= g; v1.z *= g; v1.w *= g;
        v2.x *= g; v2.y *= g; v2.z *= g; v2.w *= g;
        v3.x *= g; v3.y *= g; v3.z *= g; v3.w *= g;
        __stcs(&q[threadIdx.x], v0);
        __stcs(&q[256 + threadIdx.x], v1);
        __stcs(&q[512 + threadIdx.x], v2);
        __stcs(&q[768 + threadIdx.x], v3);
    }
}

extern "C" void kernel_launch(void* const* d_in, const int* in_sizes, int n_in,
                              void* d_out, int out_size) {
    const float* x     = (const float*)d_in[0];
    const float* grid1 = (const float*)d_in[1];
    const float* bw1   = (const float*)d_in[2];
    const float* sw1   = (const float*)d_in[3];
    const float* sc1   = (const float*)d_in[4];
    const float* grid2 = (const float*)d_in[5];
    const float* bw2   = (const float*)d_in[6];
    const float* sw2   = (const float*)d_in[7];
    const float* sc2   = (const float*)d_in[8];
    float* out = (float*)d_out;

    kanse_persistent<<<NBLOCKS, NTHREADS>>>(
        (const float4*)x, grid1, bw1, sw1, sc1,
        grid2, bw2, sw2, sc2, (float4*)out);
}